// round 13
// baseline (speedup 1.0000x reference)
#include <cuda_runtime.h>
#include <cuda_fp16.h>
#include <mma.h>
#include <math.h>

using namespace nvcuda;

#define DD 64
#define MAXNB  256
#define MAXNPAD (MAXNB * 256)
#define MAXR 256
#define MAXE 2097152

// Scratch (static device globals — no allocation anywhere; BSS zero-initialized)
__device__ unsigned g_Xh[2 * 50176 * 32]; // half2 words; row = 32 half2 = 16 uint2
__device__ unsigned g_Rh[2 * MAXR * 32];
__device__ int   g_cnt[MAXNPAD];
__device__ int   g_lex[MAXNPAD];
__device__ int   g_bsum[MAXNB];
__device__ int   g_base[MAXNB];
__device__ int   g_rank[MAXE];
__device__ uint2 g_pack2[MAXE];           // (x_row*16, r_row*16) uint2 offsets, CSR order
__device__ int   g_scanDone;              // self-resetting
__device__ int   g_scanFlag;              // reset by gather
__device__ int   g_histDone;              // reset by gather

// smem: sB half[64][136] (17408B) + sA double buffer 2 x half[64][72] (18432B)
//       + per-warp f32 scratch 8 x 16x20 (10240B) = 46080B
#define LDA 72
#define LDB 136
#define LDW 20
#define SA_BYTES (64 * LDA * 2)
#define SB_BYTES (64 * LDB * 2)
#define FSMEM (SB_BYTES + 2 * SA_BYTES + 8 * 16 * LDW * 4)

// ---------------------------------------------------------------------------
// K1 mega: [GEMM][hist][scan][rel][reorder] in one launch, overlapped via
// dispatch-order + counter/flag handshakes (monotone block dispatch).
// ---------------------------------------------------------------------------
__global__ void __launch_bounds__(256, 4) k_mega(
    const float* __restrict__ nf, const float* __restrict__ rf,
    const float* __restrict__ WI, const float* __restrict__ bI,
    const float* __restrict__ WO, const float* __restrict__ bO,
    const float* __restrict__ WR, const float* __restrict__ bR,
    float* __restrict__ r_out,
    const int* __restrict__ src, const int* __restrict__ dst,
    const int* __restrict__ et, const int* __restrict__ nrp,
    int E, int N, int R, int halfFB,
    int nbNT, int nbH, int nbScan) {

    extern __shared__ __align__(16) unsigned char smem_raw[];
    __shared__ int s[256];
    __shared__ bool amLast;

    int b = blockIdx.x;
    int tid = threadIdx.x;

    // ================= phase 1: node-transform GEMM, 256 rows/block =================
    if (b < nbNT) {
        __half* sB  = reinterpret_cast<__half*>(smem_raw);               // [k][c] ld=LDB
        __half* sA0 = reinterpret_cast<__half*>(smem_raw + SB_BYTES);
        __half* sA1 = sA0 + 64 * LDA;
        float* scratchBase = reinterpret_cast<float*>(smem_raw + SB_BYTES + 2 * SA_BYTES);

        int rowBase = b * 256;

        // weights -> fp16 smem transposed, half2-packed (ONCE per 256 rows)
        for (int i = tid; i < 64 * 16; i += 256) {
            int cw2 = i & 63;
            int k4  = (i >> 6) * 4;
            const float* Wb = (cw2 < 32) ? WI : WO;
            int c0 = (cw2 & 31) * 2;
            float4 va = *reinterpret_cast<const float4*>(Wb + c0 * 64 + k4);
            float4 vb = *reinterpret_cast<const float4*>(Wb + (c0 + 1) * 64 + k4);
            *reinterpret_cast<__half2*>(&sB[(k4 + 0) * LDB + cw2 * 2]) = __floats2half2_rn(va.x, vb.x);
            *reinterpret_cast<__half2*>(&sB[(k4 + 1) * LDB + cw2 * 2]) = __floats2half2_rn(va.y, vb.y);
            *reinterpret_cast<__half2*>(&sB[(k4 + 2) * LDB + cw2 * 2]) = __floats2half2_rn(va.z, vb.z);
            *reinterpret_cast<__half2*>(&sB[(k4 + 3) * LDB + cw2 * 2]) = __floats2half2_rn(va.w, vb.w);
        }
        // first x tile direct
#pragma unroll
        for (int it = 0; it < 4; it++) {
            int i = tid + it * 256;
            int r  = i >> 4;
            int c4 = (i & 15) * 4;
            float4 v = make_float4(0.f, 0.f, 0.f, 0.f);
            int row = rowBase + r;
            if (row < N) v = *reinterpret_cast<const float4*>(nf + (size_t)row * 64 + c4);
            *reinterpret_cast<__half2*>(&sA0[r * LDA + c4])     = __floats2half2_rn(v.x, v.y);
            *reinterpret_cast<__half2*>(&sA0[r * LDA + c4 + 2]) = __floats2half2_rn(v.z, v.w);
        }
        __syncthreads();

        int w = tid >> 5;
        int lane = tid & 31;
        int rowT = w & 3;
        int colBase = (w >> 2) * 4;
        float* swarp = scratchBase + w * (16 * LDW);

#pragma unroll
        for (int t = 0; t < 4; t++) {
            __half* sAcur  = (t & 1) ? sA1 : sA0;
            __half* sAnext = (t & 1) ? sA0 : sA1;
            int row0 = rowBase + t * 64;

            // prefetch next tile, converted to half2 immediately (8 regs not 16)
            uint2 stage[4];
            if (t < 3) {
                int rowN0 = rowBase + (t + 1) * 64;
#pragma unroll
                for (int it = 0; it < 4; it++) {
                    int i = tid + it * 256;
                    int r  = i >> 4;
                    int c4 = (i & 15) * 4;
                    int row = rowN0 + r;
                    float4 v = (row < N)
                        ? *reinterpret_cast<const float4*>(nf + (size_t)row * 64 + c4)
                        : make_float4(0.f, 0.f, 0.f, 0.f);
                    __half2 h0 = __floats2half2_rn(v.x, v.y);
                    __half2 h1 = __floats2half2_rn(v.z, v.w);
                    stage[it] = make_uint2(*reinterpret_cast<unsigned*>(&h0),
                                           *reinterpret_cast<unsigned*>(&h1));
                }
            }

            // mma on current tile
            wmma::fragment<wmma::accumulator, 16, 16, 16, float> acc[4];
#pragma unroll
            for (int j = 0; j < 4; j++) wmma::fill_fragment(acc[j], 0.0f);
#pragma unroll
            for (int kt = 0; kt < 4; kt++) {
                wmma::fragment<wmma::matrix_a, 16, 16, 16, __half, wmma::row_major> fa;
                wmma::load_matrix_sync(fa, &sAcur[(rowT * 16) * LDA + kt * 16], LDA);
#pragma unroll
                for (int j = 0; j < 4; j++) {
                    wmma::fragment<wmma::matrix_b, 16, 16, 16, __half, wmma::row_major> fb;
                    wmma::load_matrix_sync(fb, &sB[(kt * 16) * LDB + (colBase + j) * 16], LDB);
                    wmma::mma_sync(acc[j], fa, fb, acc[j]);
                }
            }

            // warp-private epilogue
#pragma unroll
            for (int j = 0; j < 4; j++) {
                wmma::store_matrix_sync(swarp, acc[j], LDW, wmma::mem_row_major);
                __syncwarp();
                int c0w = (colBase + j) * 8;
                unsigned* dstBase = (c0w < 32)
                    ? g_Xh + c0w
                    : g_Xh + (size_t)N * 32 + (c0w - 32);
#pragma unroll
                for (int q = 0; q < 2; q++) {
                    int idx = lane + 32 * q;  // 0..63
                    int r   = idx >> 2;
                    int w2  = (idx & 3) * 2;
                    float4 f = *reinterpret_cast<const float4*>(&swarp[r * LDW + w2 * 2]);
                    int row = row0 + rowT * 16 + r;
                    if (row < N) {
                        __half2 h0 = __floats2half2_rn(f.x, f.y);
                        __half2 h1 = __floats2half2_rn(f.z, f.w);
                        uint2 hv = make_uint2(*reinterpret_cast<unsigned*>(&h0),
                                              *reinterpret_cast<unsigned*>(&h1));
                        *reinterpret_cast<uint2*>(dstBase + (size_t)row * 32 + w2) = hv;
                    }
                }
                __syncwarp();
            }

            if (t < 3) {
#pragma unroll
                for (int it = 0; it < 4; it++) {
                    int i = tid + it * 256;
                    int r  = i >> 4;
                    int c4 = (i & 15) * 4;
                    *reinterpret_cast<uint2*>(&sAnext[r * LDA + c4]) = stage[it];
                }
                __syncthreads();
            }
        }
        return;
    }
    b -= nbNT;

    // ======================= phase 2: histogram + rank (16 edges/thread) =====
    if (b < nbH) {
        int t0 = (b * 256 + tid) * 16;
        if (t0 + 16 <= E) {
#pragma unroll
            for (int g = 0; g < 4; g++) {
                int4 d = *reinterpret_cast<const int4*>(dst + t0 + g * 4);
                int r0 = atomicAdd(&g_cnt[d.x], 1);
                int r1 = atomicAdd(&g_cnt[d.y], 1);
                int r2 = atomicAdd(&g_cnt[d.z], 1);
                int r3 = atomicAdd(&g_cnt[d.w], 1);
                *reinterpret_cast<int4*>(g_rank + t0 + g * 4) = make_int4(r0, r1, r2, r3);
            }
        } else {
            for (int e = t0; e < E; e++)
                g_rank[e] = atomicAdd(&g_cnt[dst[e]], 1);
        }
        __threadfence();
        __syncthreads();
        if (tid == 0) atomicAdd(&g_histDone, 1);
        return;
    }
    b -= nbH;

    // ======================= phase 3: two-level scan =======================
    if (b < nbScan) {
        if (tid == 0) {
            while (atomicAdd(&g_histDone, 0) < nbH) __nanosleep(100);
        }
        __syncthreads();
        __threadfence();

        int i = b * 256 + tid;
        int v = g_cnt[i];
        s[tid] = v;
        __syncthreads();
#pragma unroll
        for (int off = 1; off < 256; off <<= 1) {
            int x = (tid >= off) ? s[tid - off] : 0;
            __syncthreads();
            s[tid] += x;
            __syncthreads();
        }
        g_lex[i] = s[tid] - v;
        if (tid == 255) g_bsum[b] = s[tid];
        __threadfence();
        if (tid == 0) {
            int d = atomicAdd(&g_scanDone, 1);
            amLast = (d == nbScan - 1);
        }
        __syncthreads();
        if (amLast) {
            __threadfence();
            int v2 = (tid < nbScan) ? g_bsum[tid] : 0;
            s[tid] = v2;
            __syncthreads();
#pragma unroll
            for (int off = 1; off < 256; off <<= 1) {
                int x = (tid >= off) ? s[tid - off] : 0;
                __syncthreads();
                s[tid] += x;
                __syncthreads();
            }
            if (tid < nbScan) g_base[tid] = s[tid] - v2;
            __threadfence();
            __syncthreads();
            if (tid == 0) {
                g_scanDone = 0;
                atomicExch(&g_scanFlag, 1);
            }
        }
        return;
    }
    b -= nbScan;

    // ======================= phase 4: relation tables =======================
    if (b < R) {
        float* sf = reinterpret_cast<float*>(smem_raw);
        int t = b, j = tid;
        if (j < DD) sf[j] = rf[t * DD + j];
        __syncthreads();
        if (j < DD) {
            float aI = 0.f, aO = 0.f, aR = 0.f;
#pragma unroll 8
            for (int k = 0; k < DD; k++) {
                float v = sf[k];
                aI += v * WI[j * DD + k];
                aO += v * WO[j * DD + k];
                aR += v * WR[j * DD + k];
            }
            __half* Rh = reinterpret_cast<__half*>(g_Rh);
            Rh[t * DD + j]          = __float2half_rn(aI - bI[j]);
            Rh[(MAXR + t) * DD + j] = __float2half_rn(aO - bO[j]);
            r_out[t * DD + j]       = aR + bR[j];
        }
        return;
    }
    b -= R;

    // ======================= phase 5: CSR reorder (8 edges/thread) ==========
    {
        int i = b * 256 + tid;
        int half = nrp ? (__ldg(nrp) >> 1) : halfFB;
        int main8 = E >> 3;

        int4 s4a, d4a, t4a, s4b, d4b, t4b;
        bool haveMain = (i < main8);
        if (haveMain) {
            s4a = reinterpret_cast<const int4*>(src)[2 * i];
            s4b = reinterpret_cast<const int4*>(src)[2 * i + 1];
            d4a = reinterpret_cast<const int4*>(dst)[2 * i];
            d4b = reinterpret_cast<const int4*>(dst)[2 * i + 1];
            t4a = reinterpret_cast<const int4*>(et)[2 * i];
            t4b = reinterpret_cast<const int4*>(et)[2 * i + 1];
        }

        if (tid == 0) {
            while (atomicAdd(&g_scanFlag, 0) == 0) __nanosleep(100);
        }
        __syncthreads();
        __threadfence();   // acquire: g_base/g_lex/g_rank now visible

        if (haveMain) {
            int4 r4a = reinterpret_cast<const int4*>(g_rank)[2 * i];
            int4 r4b = reinterpret_cast<const int4*>(g_rank)[2 * i + 1];
            int sv[8] = {s4a.x, s4a.y, s4a.z, s4a.w, s4b.x, s4b.y, s4b.z, s4b.w};
            int dv[8] = {d4a.x, d4a.y, d4a.z, d4a.w, d4b.x, d4b.y, d4b.z, d4b.w};
            int tv[8] = {t4a.x, t4a.y, t4a.z, t4a.w, t4b.x, t4b.y, t4b.z, t4b.w};
            int rv[8] = {r4a.x, r4a.y, r4a.z, r4a.w, r4b.x, r4b.y, r4b.z, r4b.w};
#pragma unroll
            for (int u = 0; u < 8; u++) {
                int pos = g_base[dv[u] >> 8] + g_lex[dv[u]] + rv[u];
                unsigned row, trow;
                if (tv[u] < half) { row = (unsigned)sv[u];       trow = (unsigned)tv[u]; }
                else              { row = (unsigned)(sv[u] + N); trow = (unsigned)(tv[u] + MAXR); }
                g_pack2[pos] = make_uint2(row * 16u, trow * 16u);
            }
        } else if (i == main8) {
            for (int e = main8 * 8; e < E; e++) {
                int ss = src[e], dd = dst[e], tt = et[e], rr = g_rank[e];
                int pos = g_base[dd >> 8] + g_lex[dd] + rr;
                unsigned row, trow;
                if (tt < half) { row = (unsigned)ss;       trow = (unsigned)tt; }
                else           { row = (unsigned)(ss + N); trow = (unsigned)(tt + MAXR); }
                g_pack2[pos] = make_uint2(row * 16u, trow * 16u);
            }
        }
    }
}

// ---------------------------------------------------------------------------
// K2: gather + mean (R11 uint2 scheme: 2 edges/wave, 16 lanes x uint2 fp16).
// fp16 HSUB2 diff, fp32 accumulate. Resets flags/counters for next replay.
// ---------------------------------------------------------------------------
__global__ void __launch_bounds__(256) k_gather(float* __restrict__ out, int N) {
    int gid = blockIdx.x * 256 + threadIdx.x;
    if (gid == 0) { g_scanFlag = 0; g_histDone = 0; }
    int v = gid >> 5;
    if (v >= N) return;
    int lane = threadIdx.x & 31;
    int half = lane >> 4;
    int l16  = lane & 15;

    int start = g_base[v >> 8] + g_lex[v];
    int deg   = g_cnt[v];

    const uint2* __restrict__ pk2 = g_pack2 + start;
    const uint2* __restrict__ X2 = reinterpret_cast<const uint2*>(g_Xh);
    const uint2* __restrict__ R2 = reinterpret_cast<const uint2*>(g_Rh);

    float4 acc = make_float4(0.f, 0.f, 0.f, 0.f);
    int i = 0;
    for (; i + 8 <= deg; i += 8) {
#pragma unroll
        for (int u = 0; u < 4; u++) {
            uint2 p = __ldcg(&pk2[i + 2 * u + half]);
            uint2 x = __ldcg(&X2[p.x + l16]);
            uint2 r = R2[p.y + l16];
            __half2 d0 = __hsub2(*reinterpret_cast<const __half2*>(&x.x),
                                 *reinterpret_cast<const __half2*>(&r.x));
            __half2 d1 = __hsub2(*reinterpret_cast<const __half2*>(&x.y),
                                 *reinterpret_cast<const __half2*>(&r.y));
            float2 f0 = __half22float2(d0);
            float2 f1 = __half22float2(d1);
            acc.x += f0.x; acc.y += f0.y;
            acc.z += f1.x; acc.w += f1.y;
        }
    }
    for (; i < deg; i += 2) {
        if (i + half < deg) {
            uint2 p = __ldcg(&pk2[i + half]);
            uint2 x = __ldcg(&X2[p.x + l16]);
            uint2 r = R2[p.y + l16];
            __half2 d0 = __hsub2(*reinterpret_cast<const __half2*>(&x.x),
                                 *reinterpret_cast<const __half2*>(&r.x));
            __half2 d1 = __hsub2(*reinterpret_cast<const __half2*>(&x.y),
                                 *reinterpret_cast<const __half2*>(&r.y));
            float2 f0 = __half22float2(d0);
            float2 f1 = __half22float2(d1);
            acc.x += f0.x; acc.y += f0.y;
            acc.z += f1.x; acc.w += f1.y;
        }
    }
    acc.x += __shfl_xor_sync(0xffffffffu, acc.x, 16);
    acc.y += __shfl_xor_sync(0xffffffffu, acc.y, 16);
    acc.z += __shfl_xor_sync(0xffffffffu, acc.z, 16);
    acc.w += __shfl_xor_sync(0xffffffffu, acc.w, 16);

    if (half == 0) {
        float inv = 1.0f / (float)(deg > 1 ? deg : 1);
        reinterpret_cast<float4*>(out)[(size_t)v * 16 + l16] =
            make_float4(acc.x * inv, acc.y * inv, acc.z * inv, acc.w * inv);
    }
    if (lane == 0) g_cnt[v] = 0;
}

// ---------------------------------------------------------------------------
extern "C" void kernel_launch(void* const* d_in, const int* in_sizes, int n_in,
                              void* d_out, int out_size) {
    const float* nf = (const float*)d_in[0];
    const float* rf = (const float*)d_in[1];
    const float* WI = (const float*)d_in[2];
    const float* bI = (const float*)d_in[3];
    const float* WO = (const float*)d_in[4];
    const float* bO = (const float*)d_in[5];
    const float* WR = (const float*)d_in[6];
    const float* bR = (const float*)d_in[7];
    const int* src  = (const int*)d_in[8];
    const int* dst  = (const int*)d_in[9];
    const int* et   = (const int*)d_in[10];
    const int* nrp  = (n_in > 11) ? (const int*)d_in[11] : nullptr;

    int Dv = in_sizes[3];            // = 64
    int N  = in_sizes[0] / Dv;
    int R  = in_sizes[1] / Dv;
    int E  = in_sizes[8];
    float* out = (float*)d_out;
    float* r_out = out + (size_t)N * Dv;

    int nbScan = (N + 255) / 256;
    int nbNT   = (N + 255) / 256;    // 256 rows per GEMM block
    int nbH    = (E + 4095) / 4096;  // 256 thr x 16 edges
    int nbRe   = (((E >> 3) + 1) + 255) / 256;   // 256 thr x 8 edges

    static int attrSet = 0;
    if (!attrSet) {
        cudaFuncSetAttribute(k_mega, cudaFuncAttributeMaxDynamicSharedMemorySize,
                             FSMEM);
        attrSet = 1;
    }

    k_mega<<<nbNT + nbH + nbScan + R + nbRe, 256, FSMEM>>>(
        nf, rf, WI, bI, WO, bO, WR, bR, r_out,
        src, dst, et, nrp, E, N, R, R / 2, nbNT, nbH, nbScan);

    {
        long long threads = (long long)N * 32;
        k_gather<<<(int)((threads + 255) / 256), 256>>>(out, N);
    }
}

// round 14
// speedup vs baseline: 1.0833x; 1.0833x over previous
#include <cuda_runtime.h>
#include <cuda_fp16.h>
#include <mma.h>
#include <math.h>

using namespace nvcuda;

#define DD 64
#define MAXNB  256
#define MAXNPAD (MAXNB * 256)
#define MAXR 256
#define MAXE 2097152

// Scratch (static device globals — no allocation anywhere; BSS zero-initialized)
__device__ unsigned g_Xh[2 * 50176 * 32]; // half2 words; row = 32 half2 = 16 uint2
__device__ unsigned g_Rh[2 * MAXR * 32];
__device__ int   g_cnt[MAXNPAD];
__device__ int   g_lex[MAXNPAD];
__device__ int   g_bsum[MAXNB];
__device__ int   g_base[MAXNB];
__device__ int   g_rank[MAXE];
__device__ uint2 g_pack2[MAXE];           // (x_row*16, r_row*16) uint2 offsets, CSR order
__device__ int   g_scanDone;              // self-resetting
__device__ int   g_scanFlag;              // reset by gather
__device__ int   g_histDone;              // reset by gather

// smem: sB half[64][136] (17408B) + sA double buffer 2 x half[64][72] (18432B)
//       + per-warp f32 scratch 8 x 16x20 (10240B) = 46080B
#define LDA 72
#define LDB 136
#define LDW 20
#define SA_BYTES (64 * LDA * 2)
#define SB_BYTES (64 * LDB * 2)
#define FSMEM (SB_BYTES + 2 * SA_BYTES + 8 * 16 * LDW * 4)

// ---------------------------------------------------------------------------
// K1 mega (R12 configuration — best measured): [GEMM][hist][scan][rel][reorder]
// one launch, overlapped via dispatch-order + counter/flag handshakes.
// ---------------------------------------------------------------------------
__global__ void __launch_bounds__(256, 3) k_mega(
    const float* __restrict__ nf, const float* __restrict__ rf,
    const float* __restrict__ WI, const float* __restrict__ bI,
    const float* __restrict__ WO, const float* __restrict__ bO,
    const float* __restrict__ WR, const float* __restrict__ bR,
    float* __restrict__ r_out,
    const int* __restrict__ src, const int* __restrict__ dst,
    const int* __restrict__ et, const int* __restrict__ nrp,
    int E, int N, int R, int halfFB,
    int nbNT, int nbH, int nbScan) {

    extern __shared__ __align__(16) unsigned char smem_raw[];
    __shared__ int s[256];
    __shared__ bool amLast;

    int b = blockIdx.x;
    int tid = threadIdx.x;

    // ================= phase 1: node-transform GEMM, 256 rows/block =================
    if (b < nbNT) {
        __half* sB  = reinterpret_cast<__half*>(smem_raw);               // [k][c] ld=LDB
        __half* sA0 = reinterpret_cast<__half*>(smem_raw + SB_BYTES);
        __half* sA1 = sA0 + 64 * LDA;
        float* scratchBase = reinterpret_cast<float*>(smem_raw + SB_BYTES + 2 * SA_BYTES);

        int rowBase = b * 256;

        // weights -> fp16 smem transposed, half2-packed (ONCE per 256 rows)
        for (int i = tid; i < 64 * 16; i += 256) {
            int cw2 = i & 63;
            int k4  = (i >> 6) * 4;
            const float* Wb = (cw2 < 32) ? WI : WO;
            int c0 = (cw2 & 31) * 2;
            float4 va = *reinterpret_cast<const float4*>(Wb + c0 * 64 + k4);
            float4 vb = *reinterpret_cast<const float4*>(Wb + (c0 + 1) * 64 + k4);
            *reinterpret_cast<__half2*>(&sB[(k4 + 0) * LDB + cw2 * 2]) = __floats2half2_rn(va.x, vb.x);
            *reinterpret_cast<__half2*>(&sB[(k4 + 1) * LDB + cw2 * 2]) = __floats2half2_rn(va.y, vb.y);
            *reinterpret_cast<__half2*>(&sB[(k4 + 2) * LDB + cw2 * 2]) = __floats2half2_rn(va.z, vb.z);
            *reinterpret_cast<__half2*>(&sB[(k4 + 3) * LDB + cw2 * 2]) = __floats2half2_rn(va.w, vb.w);
        }
        // first x tile direct
#pragma unroll
        for (int it = 0; it < 4; it++) {
            int i = tid + it * 256;
            int r  = i >> 4;
            int c4 = (i & 15) * 4;
            float4 v = make_float4(0.f, 0.f, 0.f, 0.f);
            int row = rowBase + r;
            if (row < N) v = *reinterpret_cast<const float4*>(nf + (size_t)row * 64 + c4);
            *reinterpret_cast<__half2*>(&sA0[r * LDA + c4])     = __floats2half2_rn(v.x, v.y);
            *reinterpret_cast<__half2*>(&sA0[r * LDA + c4 + 2]) = __floats2half2_rn(v.z, v.w);
        }
        __syncthreads();

        int w = tid >> 5;
        int lane = tid & 31;
        int rowT = w & 3;
        int colBase = (w >> 2) * 4;
        float* swarp = scratchBase + w * (16 * LDW);

#pragma unroll
        for (int t = 0; t < 4; t++) {
            __half* sAcur  = (t & 1) ? sA1 : sA0;
            __half* sAnext = (t & 1) ? sA0 : sA1;
            int row0 = rowBase + t * 64;

            // prefetch next tile into registers (hidden under mma+epilogue)
            float4 stage[4];
            if (t < 3) {
                int rowN0 = rowBase + (t + 1) * 64;
#pragma unroll
                for (int it = 0; it < 4; it++) {
                    int i = tid + it * 256;
                    int r  = i >> 4;
                    int c4 = (i & 15) * 4;
                    int row = rowN0 + r;
                    stage[it] = (row < N)
                        ? *reinterpret_cast<const float4*>(nf + (size_t)row * 64 + c4)
                        : make_float4(0.f, 0.f, 0.f, 0.f);
                }
            }

            // mma on current tile
            wmma::fragment<wmma::accumulator, 16, 16, 16, float> acc[4];
#pragma unroll
            for (int j = 0; j < 4; j++) wmma::fill_fragment(acc[j], 0.0f);
#pragma unroll
            for (int kt = 0; kt < 4; kt++) {
                wmma::fragment<wmma::matrix_a, 16, 16, 16, __half, wmma::row_major> fa;
                wmma::load_matrix_sync(fa, &sAcur[(rowT * 16) * LDA + kt * 16], LDA);
#pragma unroll
                for (int j = 0; j < 4; j++) {
                    wmma::fragment<wmma::matrix_b, 16, 16, 16, __half, wmma::row_major> fb;
                    wmma::load_matrix_sync(fb, &sB[(kt * 16) * LDB + (colBase + j) * 16], LDB);
                    wmma::mma_sync(acc[j], fa, fb, acc[j]);
                }
            }

            // warp-private epilogue
#pragma unroll
            for (int j = 0; j < 4; j++) {
                wmma::store_matrix_sync(swarp, acc[j], LDW, wmma::mem_row_major);
                __syncwarp();
                int c0w = (colBase + j) * 8;
                unsigned* dstBase = (c0w < 32)
                    ? g_Xh + c0w
                    : g_Xh + (size_t)N * 32 + (c0w - 32);
#pragma unroll
                for (int q = 0; q < 2; q++) {
                    int idx = lane + 32 * q;  // 0..63
                    int r   = idx >> 2;
                    int w2  = (idx & 3) * 2;
                    float4 f = *reinterpret_cast<const float4*>(&swarp[r * LDW + w2 * 2]);
                    int row = row0 + rowT * 16 + r;
                    if (row < N) {
                        __half2 h0 = __floats2half2_rn(f.x, f.y);
                        __half2 h1 = __floats2half2_rn(f.z, f.w);
                        uint2 hv = make_uint2(*reinterpret_cast<unsigned*>(&h0),
                                              *reinterpret_cast<unsigned*>(&h1));
                        *reinterpret_cast<uint2*>(dstBase + (size_t)row * 32 + w2) = hv;
                    }
                }
                __syncwarp();
            }

            if (t < 3) {
#pragma unroll
                for (int it = 0; it < 4; it++) {
                    int i = tid + it * 256;
                    int r  = i >> 4;
                    int c4 = (i & 15) * 4;
                    *reinterpret_cast<__half2*>(&sAnext[r * LDA + c4])     = __floats2half2_rn(stage[it].x, stage[it].y);
                    *reinterpret_cast<__half2*>(&sAnext[r * LDA + c4 + 2]) = __floats2half2_rn(stage[it].z, stage[it].w);
                }
                __syncthreads();
            }
        }
        return;
    }
    b -= nbNT;

    // ======================= phase 2: histogram + rank (8 edges/thread) ======
    if (b < nbH) {
        int t0 = (b * 256 + tid) * 8;
        if (t0 + 8 <= E) {
            int4 d0 = *reinterpret_cast<const int4*>(dst + t0);
            int4 d1 = *reinterpret_cast<const int4*>(dst + t0 + 4);
            int r0 = atomicAdd(&g_cnt[d0.x], 1);
            int r1 = atomicAdd(&g_cnt[d0.y], 1);
            int r2 = atomicAdd(&g_cnt[d0.z], 1);
            int r3 = atomicAdd(&g_cnt[d0.w], 1);
            int r4 = atomicAdd(&g_cnt[d1.x], 1);
            int r5 = atomicAdd(&g_cnt[d1.y], 1);
            int r6 = atomicAdd(&g_cnt[d1.z], 1);
            int r7 = atomicAdd(&g_cnt[d1.w], 1);
            *reinterpret_cast<int4*>(g_rank + t0)     = make_int4(r0, r1, r2, r3);
            *reinterpret_cast<int4*>(g_rank + t0 + 4) = make_int4(r4, r5, r6, r7);
        } else {
            for (int e = t0; e < E; e++)
                g_rank[e] = atomicAdd(&g_cnt[dst[e]], 1);
        }
        __threadfence();
        __syncthreads();
        if (tid == 0) atomicAdd(&g_histDone, 1);
        return;
    }
    b -= nbH;

    // ======================= phase 3: two-level scan =======================
    if (b < nbScan) {
        if (tid == 0) {
            while (atomicAdd(&g_histDone, 0) < nbH) __nanosleep(100);
        }
        __syncthreads();
        __threadfence();

        int i = b * 256 + tid;
        int v = g_cnt[i];
        s[tid] = v;
        __syncthreads();
#pragma unroll
        for (int off = 1; off < 256; off <<= 1) {
            int x = (tid >= off) ? s[tid - off] : 0;
            __syncthreads();
            s[tid] += x;
            __syncthreads();
        }
        g_lex[i] = s[tid] - v;
        if (tid == 255) g_bsum[b] = s[tid];
        __threadfence();
        if (tid == 0) {
            int d = atomicAdd(&g_scanDone, 1);
            amLast = (d == nbScan - 1);
        }
        __syncthreads();
        if (amLast) {
            __threadfence();
            int v2 = (tid < nbScan) ? g_bsum[tid] : 0;
            s[tid] = v2;
            __syncthreads();
#pragma unroll
            for (int off = 1; off < 256; off <<= 1) {
                int x = (tid >= off) ? s[tid - off] : 0;
                __syncthreads();
                s[tid] += x;
                __syncthreads();
            }
            if (tid < nbScan) g_base[tid] = s[tid] - v2;
            __threadfence();
            __syncthreads();
            if (tid == 0) {
                g_scanDone = 0;
                atomicExch(&g_scanFlag, 1);
            }
        }
        return;
    }
    b -= nbScan;

    // ======================= phase 4: relation tables =======================
    if (b < R) {
        float* sf = reinterpret_cast<float*>(smem_raw);
        int t = b, j = tid;
        if (j < DD) sf[j] = rf[t * DD + j];
        __syncthreads();
        if (j < DD) {
            float aI = 0.f, aO = 0.f, aR = 0.f;
#pragma unroll 8
            for (int k = 0; k < DD; k++) {
                float v = sf[k];
                aI += v * WI[j * DD + k];
                aO += v * WO[j * DD + k];
                aR += v * WR[j * DD + k];
            }
            __half* Rh = reinterpret_cast<__half*>(g_Rh);
            Rh[t * DD + j]          = __float2half_rn(aI - bI[j]);
            Rh[(MAXR + t) * DD + j] = __float2half_rn(aO - bO[j]);
            r_out[t * DD + j]       = aR + bR[j];
        }
        return;
    }
    b -= R;

    // ======================= phase 5: CSR reorder (4 edges/thread) ==========
    {
        int i = b * 256 + tid;
        int half = nrp ? (__ldg(nrp) >> 1) : halfFB;
        int main4 = E >> 2;

        int4 s4, d4, t4;
        bool haveMain = (i < main4);
        if (haveMain) {
            s4 = reinterpret_cast<const int4*>(src)[i];
            d4 = reinterpret_cast<const int4*>(dst)[i];
            t4 = reinterpret_cast<const int4*>(et)[i];
        }

        if (tid == 0) {
            while (atomicAdd(&g_scanFlag, 0) == 0) __nanosleep(200);
        }
        __syncthreads();
        __threadfence();   // acquire: g_base/g_lex/g_rank now visible

        if (haveMain) {
            int4 r4 = reinterpret_cast<const int4*>(g_rank)[i];
#pragma unroll
            for (int u = 0; u < 4; u++) {
                int ss = (u == 0) ? s4.x : (u == 1) ? s4.y : (u == 2) ? s4.z : s4.w;
                int dd = (u == 0) ? d4.x : (u == 1) ? d4.y : (u == 2) ? d4.z : d4.w;
                int tt = (u == 0) ? t4.x : (u == 1) ? t4.y : (u == 2) ? t4.z : t4.w;
                int rr = (u == 0) ? r4.x : (u == 1) ? r4.y : (u == 2) ? r4.z : r4.w;
                int pos = g_base[dd >> 8] + g_lex[dd] + rr;
                unsigned row, trow;
                if (tt < half) { row = (unsigned)ss;       trow = (unsigned)tt; }
                else           { row = (unsigned)(ss + N); trow = (unsigned)(tt + MAXR); }
                g_pack2[pos] = make_uint2(row * 16u, trow * 16u);
            }
        } else if (i == main4) {
            for (int e = main4 * 4; e < E; e++) {
                int ss = src[e], dd = dst[e], tt = et[e], rr = g_rank[e];
                int pos = g_base[dd >> 8] + g_lex[dd] + rr;
                unsigned row, trow;
                if (tt < half) { row = (unsigned)ss;       trow = (unsigned)tt; }
                else           { row = (unsigned)(ss + N); trow = (unsigned)(tt + MAXR); }
                g_pack2[pos] = make_uint2(row * 16u, trow * 16u);
            }
        }
    }
}

// ---------------------------------------------------------------------------
// K2: gather + mean (R11 uint2 scheme: 2 edges/wave, 16 lanes x uint2 fp16).
// fp16 HSUB2 diff, fp32 accumulate. Resets flags/counters for next replay.
// ---------------------------------------------------------------------------
__global__ void __launch_bounds__(256) k_gather(float* __restrict__ out, int N) {
    int gid = blockIdx.x * 256 + threadIdx.x;
    if (gid == 0) { g_scanFlag = 0; g_histDone = 0; }
    int v = gid >> 5;
    if (v >= N) return;
    int lane = threadIdx.x & 31;
    int half = lane >> 4;
    int l16  = lane & 15;

    int start = g_base[v >> 8] + g_lex[v];
    int deg   = g_cnt[v];

    const uint2* __restrict__ pk2 = g_pack2 + start;
    const uint2* __restrict__ X2 = reinterpret_cast<const uint2*>(g_Xh);
    const uint2* __restrict__ R2 = reinterpret_cast<const uint2*>(g_Rh);

    float4 acc = make_float4(0.f, 0.f, 0.f, 0.f);
    int i = 0;
    for (; i + 8 <= deg; i += 8) {
#pragma unroll
        for (int u = 0; u < 4; u++) {
            uint2 p = __ldcg(&pk2[i + 2 * u + half]);
            uint2 x = __ldcg(&X2[p.x + l16]);
            uint2 r = R2[p.y + l16];
            __half2 d0 = __hsub2(*reinterpret_cast<const __half2*>(&x.x),
                                 *reinterpret_cast<const __half2*>(&r.x));
            __half2 d1 = __hsub2(*reinterpret_cast<const __half2*>(&x.y),
                                 *reinterpret_cast<const __half2*>(&r.y));
            float2 f0 = __half22float2(d0);
            float2 f1 = __half22float2(d1);
            acc.x += f0.x; acc.y += f0.y;
            acc.z += f1.x; acc.w += f1.y;
        }
    }
    for (; i < deg; i += 2) {
        if (i + half < deg) {
            uint2 p = __ldcg(&pk2[i + half]);
            uint2 x = __ldcg(&X2[p.x + l16]);
            uint2 r = R2[p.y + l16];
            __half2 d0 = __hsub2(*reinterpret_cast<const __half2*>(&x.x),
                                 *reinterpret_cast<const __half2*>(&r.x));
            __half2 d1 = __hsub2(*reinterpret_cast<const __half2*>(&x.y),
                                 *reinterpret_cast<const __half2*>(&r.y));
            float2 f0 = __half22float2(d0);
            float2 f1 = __half22float2(d1);
            acc.x += f0.x; acc.y += f0.y;
            acc.z += f1.x; acc.w += f1.y;
        }
    }
    acc.x += __shfl_xor_sync(0xffffffffu, acc.x, 16);
    acc.y += __shfl_xor_sync(0xffffffffu, acc.y, 16);
    acc.z += __shfl_xor_sync(0xffffffffu, acc.z, 16);
    acc.w += __shfl_xor_sync(0xffffffffu, acc.w, 16);

    if (half == 0) {
        float inv = 1.0f / (float)(deg > 1 ? deg : 1);
        reinterpret_cast<float4*>(out)[(size_t)v * 16 + l16] =
            make_float4(acc.x * inv, acc.y * inv, acc.z * inv, acc.w * inv);
    }
    if (lane == 0) g_cnt[v] = 0;
}

// ---------------------------------------------------------------------------
extern "C" void kernel_launch(void* const* d_in, const int* in_sizes, int n_in,
                              void* d_out, int out_size) {
    const float* nf = (const float*)d_in[0];
    const float* rf = (const float*)d_in[1];
    const float* WI = (const float*)d_in[2];
    const float* bI = (const float*)d_in[3];
    const float* WO = (const float*)d_in[4];
    const float* bO = (const float*)d_in[5];
    const float* WR = (const float*)d_in[6];
    const float* bR = (const float*)d_in[7];
    const int* src  = (const int*)d_in[8];
    const int* dst  = (const int*)d_in[9];
    const int* et   = (const int*)d_in[10];
    const int* nrp  = (n_in > 11) ? (const int*)d_in[11] : nullptr;

    int Dv = in_sizes[3];            // = 64
    int N  = in_sizes[0] / Dv;
    int R  = in_sizes[1] / Dv;
    int E  = in_sizes[8];
    float* out = (float*)d_out;
    float* r_out = out + (size_t)N * Dv;

    int nbScan = (N + 255) / 256;
    int nbNT   = (N + 255) / 256;    // 256 rows per GEMM block
    int nbH    = (E + 2047) / 2048;  // 256 thr x 8 edges
    int nbRe   = (((E >> 2) + 1) + 255) / 256;   // 256 thr x 4 edges

    static int attrSet = 0;
    if (!attrSet) {
        cudaFuncSetAttribute(k_mega, cudaFuncAttributeMaxDynamicSharedMemorySize,
                             FSMEM);
        attrSet = 1;
    }

    k_mega<<<nbNT + nbH + nbScan + R + nbRe, 256, FSMEM>>>(
        nf, rf, WI, bI, WO, bO, WR, bR, r_out,
        src, dst, et, nrp, E, N, R, R / 2, nbNT, nbH, nbScan);

    {
        long long threads = (long long)N * 32;
        k_gather<<<(int)((threads + 255) / 256), 256>>>(out, N);
    }
}